// round 7
// baseline (speedup 1.0000x reference)
#include <cuda_runtime.h>
#include <cuda_fp16.h>
#include <cstdint>

// ============================================================
// Problem constants
// ============================================================
#define M_TOTAL   65536          // B*NP = 16*4096
#define K_DIM     768
#define N_DIM     1152
#define POS_SIZE  64

// Tiling
#define M_TILE    128
#define N_TILE    128
#define K_CHUNK   16                       // k elems per double-buffer chunk
#define NUM_CHUNKS (K_DIM / K_CHUNK)       // 48

// smem tile: [row][12 x u32]; cols 0..7 = 16 halfs of the k-chunk, 8..11 pad.
// Bank pattern of fragment loads (addr32 = 12*r + q, r=0..7, q=0..3):
// 12r mod 32 = {0,12,24,4,16,28,8,20} -> disjoint 4-word blocks: conflict-free.
#define ROW_U32   12

__device__ int g_pos_is_i32;    // 1 if position ids are int32, 0 if int64
__device__ int g_pad_is_i32;    // 1 if padding mask is int32, 0 if 1-byte bool

// ============================================================
// Dtype detectors.
// pos: int64 layout -> odd 32-bit words are high words of values in [0,64),
//      i.e. all zero. int32 layout -> odd words are y coords, not all zero.
// pad: byte-bool layout -> int32 view of the first 65536 bytes contains words
//      with bits set above bit 0 (packed 0/1 bytes) with overwhelming prob.
//      int32-bool layout -> every word is 0 or 1.
// Reading 16384 words = 65536 bytes is in-bounds under BOTH interpretations.
// ============================================================
__global__ void detect_kernel(const int* __restrict__ pos,
                              const int* __restrict__ padw) {
    __shared__ int sh[256];
    int acc = 0;
    if (blockIdx.x == 0) {
        for (int t = threadIdx.x; t < 2048; t += 256)
            acc |= pos[2 * t + 1];
    } else {
        for (int t = threadIdx.x; t < 16384; t += 256)
            acc |= (padw[t] & ~1);     // any bit beyond bit0 -> byte layout
    }
    sh[threadIdx.x] = acc;
    __syncthreads();
    for (int s = 128; s > 0; s >>= 1) {
        if (threadIdx.x < s) sh[threadIdx.x] |= sh[threadIdx.x + s];
        __syncthreads();
    }
    if (threadIdx.x == 0) {
        if (blockIdx.x == 0) g_pos_is_i32 = (sh[0] != 0) ? 1 : 0;
        else                 g_pad_is_i32 = (sh[0] != 0) ? 0 : 1;
    }
}

// ============================================================
// MMA m16n8k16 row.col f32.f16.f16.f32  (PTX ISA fragment layouts)
// A frag (4 regs, thread l, r=l>>2, q=l&3): a0=A[r][2q,2q+1], a1=A[r+8][2q..],
//   a2=A[r][8+2q..], a3=A[r+8][8+2q..]
// B frag (2 regs): b0=B[2q..2q+1][n=r], b1=B[8+2q..][n]
// C frag (4 regs): c0=(r,2q) c1=(r,2q+1) c2=(r+8,2q) c3=(r+8,2q+1)
// ============================================================
#define MMA16816(C, A, B) \
    asm volatile("mma.sync.aligned.m16n8k16.row.col.f32.f16.f16.f32 " \
        "{%0,%1,%2,%3}, {%4,%5,%6,%7}, {%8,%9}, {%0,%1,%2,%3};" \
        : "+f"((C)[0]), "+f"((C)[1]), "+f"((C)[2]), "+f"((C)[3]) \
        : "r"((A)[0]), "r"((A)[1]), "r"((A)[2]), "r"((A)[3]), \
          "r"((B)[0]), "r"((B)[1]))

__device__ __forceinline__ uint32_t h2bits(__half2 h) {
    return *reinterpret_cast<uint32_t*>(&h);
}

// ============================================================
// GEMM + positional-embedding epilogue
//   grid = (N_DIM/128, M_TOTAL/128), block = 256 (8 warps)
//   warp grid 4(m) x 2(n): warp tile 32 x 64
// ============================================================
__global__ void __launch_bounds__(256, 2) gemm_kernel(
    const float* __restrict__ px,               // [M_TOTAL, 768] f32
    const void* __restrict__ pos_raw,           // [M_TOTAL, 2] i32 or i64
    const void* __restrict__ pad_raw,           // [M_TOTAL] i32 or u8
    const float* __restrict__ W,                // [1152, 768] f32
    const float* __restrict__ table,            // [2, 64, 1152] f32
    float* __restrict__ out)                    // [M_TOTAL, 1152] f32
{
    // [stage][0=A,1=B][row][col]: 2*2*128*12*4 = 49152 bytes
    __shared__ uint32_t sh[2][2][M_TILE][ROW_U32];

    const int tid  = threadIdx.x;
    const int lane = tid & 31;
    const int wid  = tid >> 5;
    const int wm   = wid & 3;          // 0..3  -> rows 32*wm
    const int wn   = wid >> 2;         // 0..1  -> cols 64*wn
    const int m_base = blockIdx.y * M_TILE;
    const int n_base = blockIdx.x * N_TILE;

    // Global staging: per chunk, tile = 128 rows x 16 f32 = 512 float4;
    // 256 threads x 2. idx -> (row = idx>>2, seg = idx&3).
    const int row0 = tid >> 2;
    const int seg0 = tid & 3;

    float4 fa[2], fb[2];

    auto gload = [&](int c) {
        const int kb = c * K_CHUNK;
#pragma unroll
        for (int j = 0; j < 2; j++) {
            const int row = row0 + 64 * j;
            fa[j] = *reinterpret_cast<const float4*>(
                px + (size_t)(m_base + row) * K_DIM + kb + seg0 * 4);
            fb[j] = *reinterpret_cast<const float4*>(
                W + (size_t)(n_base + row) * K_DIM + kb + seg0 * 4);
        }
    };
    auto sstore = [&](int s) {
#pragma unroll
        for (int j = 0; j < 2; j++) {
            const int row = row0 + 64 * j;
            sh[s][0][row][seg0 * 2 + 0] = h2bits(__floats2half2_rn(fa[j].x, fa[j].y));
            sh[s][0][row][seg0 * 2 + 1] = h2bits(__floats2half2_rn(fa[j].z, fa[j].w));
            sh[s][1][row][seg0 * 2 + 0] = h2bits(__floats2half2_rn(fb[j].x, fb[j].y));
            sh[s][1][row][seg0 * 2 + 1] = h2bits(__floats2half2_rn(fb[j].z, fb[j].w));
        }
    };

    float acc[2][8][4];
#pragma unroll
    for (int i = 0; i < 2; i++)
#pragma unroll
        for (int j = 0; j < 8; j++)
#pragma unroll
            for (int e = 0; e < 4; e++) acc[i][j][e] = 0.0f;

    const int r4 = lane >> 2;   // 0..7
    const int q  = lane & 3;    // 0..3

    gload(0);
    sstore(0);

#pragma unroll 1
    for (int c = 0; c < NUM_CHUNKS; c++) {
        if (c + 1 < NUM_CHUNKS) gload(c + 1);    // register-private, no hazard
        __syncthreads();                          // stage c&1 stores visible
        const int s = c & 1;

        uint32_t bf[8][2];
#pragma unroll
        for (int j = 0; j < 8; j++) {
            const int n = wn * 64 + j * 8 + r4;
            bf[j][0] = sh[s][1][n][q];
            bf[j][1] = sh[s][1][n][q + 4];
        }
#pragma unroll
        for (int i = 0; i < 2; i++) {
            const int r = wm * 32 + i * 16 + r4;
            uint32_t af[4];
            af[0] = sh[s][0][r][q];
            af[1] = sh[s][0][r + 8][q];
            af[2] = sh[s][0][r][q + 4];
            af[3] = sh[s][0][r + 8][q + 4];
#pragma unroll
            for (int j = 0; j < 8; j++)
                MMA16816(acc[i][j], af, bf[j]);
        }
        __syncthreads();                          // all reads of old stage done
        if (c + 1 < NUM_CHUNKS) sstore((c + 1) & 1);
    }

    // ---------------- Epilogue: + positional embedding, store ----------------
    const int qc = q * 2;
    const int pos_i32 = g_pos_is_i32;
    const int pad_i32 = g_pad_is_i32;
    const int* p32 = (const int*)pos_raw;
    const long long* p64 = (const long long*)pos_raw;
    const int* pd32 = (const int*)pad_raw;
    const unsigned char* pd8 = (const unsigned char*)pad_raw;

#pragma unroll
    for (int i = 0; i < 2; i++) {
#pragma unroll
        for (int rh = 0; rh < 2; rh++) {
            const int m = m_base + wm * 32 + i * 16 + rh * 8 + r4;
            int xr, yr;
            if (pos_i32) {
                xr = p32[(size_t)m * 2 + 0];
                yr = p32[(size_t)m * 2 + 1];
            } else {
                long long pxv = p64[(size_t)m * 2 + 0];
                long long pyv = p64[(size_t)m * 2 + 1];
                xr = (pxv < 0) ? 0 : (pxv > 63 ? 63 : (int)pxv);
                yr = (pyv < 0) ? 0 : (pyv > 63 ? 63 : (int)pyv);
            }
            // Clamp (ref clips at 0; values < 64). Also makes any dtype
            // misinterpretation non-faulting.
            const int xi = (xr < 0) ? 0 : (xr > 63 ? 63 : xr);
            const int yi = (yr < 0) ? 0 : (yr > 63 ? 63 : yr);
            const bool pd = pad_i32 ? (pd32[m] != 0) : (pd8[m] != 0);
            const float* t0 = table + (size_t)xi * N_DIM;
            const float* t1 = table + (size_t)(POS_SIZE + yi) * N_DIM;
            float* orow = out + (size_t)m * N_DIM;
#pragma unroll
            for (int j = 0; j < 8; j++) {
                const int n = n_base + wn * 64 + j * 8 + qc;
                float v0 = acc[i][j][rh * 2 + 0];
                float v1 = acc[i][j][rh * 2 + 1];
                if (!pd) {
                    const float2 a = *reinterpret_cast<const float2*>(t0 + n);
                    const float2 b = *reinterpret_cast<const float2*>(t1 + n);
                    v0 += a.x + b.x;
                    v1 += a.y + b.y;
                }
                float2 o; o.x = v0; o.y = v1;
                *reinterpret_cast<float2*>(orow + n) = o;
            }
        }
    }
}

// ============================================================
// Launch — inputs identified by element count (all distinct):
//   pixel_values 50331648, pos 131072, pad 65536, W 884736, table 147456
// ============================================================
extern "C" void kernel_launch(void* const* d_in, const int* in_sizes, int n_in,
                              void* d_out, int out_size) {
    const float* px = nullptr;
    const void*  pos = nullptr;
    const void*  pad = nullptr;
    const float* W = nullptr;
    const float* table = nullptr;

    for (int i = 0; i < n_in; i++) {
        switch (in_sizes[i]) {
            case 50331648: px    = (const float*)d_in[i]; break;
            case 131072:   pos   = d_in[i];               break;
            case 65536:    pad   = d_in[i];               break;
            case 884736:   W     = (const float*)d_in[i]; break;
            case 147456:   table = (const float*)d_in[i]; break;
            default: break;
        }
    }
    // Fallback to declared order if any lookup failed
    if (!px)    px    = (const float*)d_in[0];
    if (!pos)   pos   = d_in[1];
    if (!pad)   pad   = d_in[2];
    if (!W)     W     = (const float*)d_in[3];
    if (!table) table = (const float*)d_in[4];

    float* out = (float*)d_out;

    detect_kernel<<<2, 256>>>((const int*)pos, (const int*)pad);

    dim3 grid(N_DIM / N_TILE, M_TOTAL / M_TILE);   // (9, 512) — N fastest: A reuse
    gemm_kernel<<<grid, 256>>>(px, pos, pad, W, table, out);
}

// round 8
// speedup vs baseline: 1.4549x; 1.4549x over previous
#include <cuda_runtime.h>
#include <cuda_fp16.h>
#include <cstdint>

// ============================================================
// Problem constants
// ============================================================
#define M_TOTAL   65536          // B*NP = 16*4096
#define K_DIM     768
#define N_DIM     1152
#define POS_SIZE  64

// Tiling
#define M_TILE    128
#define N_TILE    128
#define K_CHUNK   32                       // fp16 elems per pipeline chunk
#define NUM_CHUNKS (K_DIM / K_CHUNK)       // 24
#define STAGES    4

// SMEM rows padded 64B->80B. ldmatrix row addrs r*80 mod 128 =
// {0,80,32,112,64,16,96,48} for r=0..7 -> distinct 16B banks: conflict-free.
#define ROW_BYTES   80
#define TILE_BYTES  (128 * ROW_BYTES)      // 10240
#define STAGE_BYTES (2 * TILE_BYTES)       // 20480 (A then B)
#define SMEM_TOTAL  (STAGES * STAGE_BYTES) // 81920

// ============================================================
// Scratch (device globals -- no allocation)
// ============================================================
__device__ __align__(256) __half g_A[(size_t)M_TOTAL * K_DIM];   // 96 MB
__device__ __align__(256) __half g_B[(size_t)N_DIM * K_DIM];     // 1.7 MB
__device__ int g_pos_is_i32;    // 1 if position ids are int32, 0 if int64
__device__ int g_pad_is_i32;    // 1 if padding mask is int32, 0 if 1-byte bool

// ============================================================
// Dtype detectors (verified R6).
// ============================================================
__global__ void detect_kernel(const int* __restrict__ pos,
                              const int* __restrict__ padw) {
    __shared__ int sh[256];
    int acc = 0;
    if (blockIdx.x == 0) {
        for (int t = threadIdx.x; t < 2048; t += 256)
            acc |= pos[2 * t + 1];
    } else {
        for (int t = threadIdx.x; t < 16384; t += 256)
            acc |= (padw[t] & ~1);     // any bit beyond bit0 -> byte layout
    }
    sh[threadIdx.x] = acc;
    __syncthreads();
    for (int s = 128; s > 0; s >>= 1) {
        if (threadIdx.x < s) sh[threadIdx.x] |= sh[threadIdx.x + s];
        __syncthreads();
    }
    if (threadIdx.x == 0) {
        if (blockIdx.x == 0) g_pos_is_i32 = (sh[0] != 0) ? 1 : 0;
        else                 g_pad_is_i32 = (sh[0] != 0) ? 0 : 1;
    }
}

// ============================================================
// Helpers
// ============================================================
__device__ __forceinline__ uint32_t smem_u32(const void* p) {
    uint32_t a;
    asm("{ .reg .u64 t; cvta.to.shared.u64 t, %1; cvt.u32.u64 %0, t; }"
        : "=r"(a) : "l"(p));
    return a;
}

#define CP_ASYNC16(saddr, gptr) \
    asm volatile("cp.async.cg.shared.global [%0], [%1], 16;" \
                 :: "r"(saddr), "l"(gptr) : "memory")
#define CP_COMMIT() asm volatile("cp.async.commit_group;" ::: "memory")
#define CP_WAIT2()  asm volatile("cp.async.wait_group 2;" ::: "memory")

#define LDMX4(R, addr) \
    asm volatile("ldmatrix.sync.aligned.m8n8.x4.shared.b16 {%0,%1,%2,%3}, [%4];" \
        : "=r"((R)[0]), "=r"((R)[1]), "=r"((R)[2]), "=r"((R)[3]) : "r"(addr))

// mma.sync m16n8k16 row.col f32.f16.f16.f32 (PTX ISA fragment layouts;
// lane maps verified equivalent to the R5/R6 scalar-load kernel).
#define MMA16816(C, A, B) \
    asm volatile("mma.sync.aligned.m16n8k16.row.col.f32.f16.f16.f32 " \
        "{%0,%1,%2,%3}, {%4,%5,%6,%7}, {%8,%9}, {%0,%1,%2,%3};" \
        : "+f"((C)[0]), "+f"((C)[1]), "+f"((C)[2]), "+f"((C)[3]) \
        : "r"((A)[0]), "r"((A)[1]), "r"((A)[2]), "r"((A)[3]), \
          "r"((B)[0]), "r"((B)[1]))

// ============================================================
// Prep kernels: fp32 -> fp16 (same rounding as R6's in-kernel convert)
// ============================================================
__device__ __forceinline__ uint2 cvt4(float4 v) {
    __half2 h0 = __floats2half2_rn(v.x, v.y);
    __half2 h1 = __floats2half2_rn(v.z, v.w);
    uint2 o;
    o.x = *reinterpret_cast<uint32_t*>(&h0);
    o.y = *reinterpret_cast<uint32_t*>(&h1);
    return o;
}

__global__ void prep_a_kernel(const float4* __restrict__ src, int n4) {
    int i = blockIdx.x * blockDim.x + threadIdx.x;
    if (i < n4) reinterpret_cast<uint2*>(g_A)[i] = cvt4(src[i]);
}

__global__ void prep_b_kernel(const float4* __restrict__ src, int n4) {
    int i = blockIdx.x * blockDim.x + threadIdx.x;
    if (i < n4) reinterpret_cast<uint2*>(g_B)[i] = cvt4(src[i]);
}

// ============================================================
// GEMM + positional-embedding epilogue
//   grid = (N_DIM/128, M_TOTAL/128), block = 256 (8 warps)
//   warp grid 4(m) x 2(n): warp tile 32 x 64
// ============================================================
__global__ void __launch_bounds__(256, 2) gemm_kernel(
    const void* __restrict__ pos_raw,           // [M_TOTAL, 2] i32 or i64
    const void* __restrict__ pad_raw,           // [M_TOTAL] i32 or u8
    const float* __restrict__ table,            // [2, 64, 1152] f32
    float* __restrict__ out)                    // [M_TOTAL, 1152] f32
{
    extern __shared__ char smem[];
    const uint32_t sbase = smem_u32(smem);
    const int tid  = threadIdx.x;
    const int lane = tid & 31;
    const int wid  = tid >> 5;
    const int wm   = wid & 3;          // 0..3  -> rows 32*wm
    const int wn   = wid >> 2;         // 0..1  -> cols 64*wn
    const int m_base = blockIdx.y * M_TILE;
    const int n_base = blockIdx.x * N_TILE;

    const __half* gA = g_A + (size_t)m_base * K_DIM;
    const __half* gB = g_B + (size_t)n_base * K_DIM;

    // cp.async decomposition: per tile 128 rows x 64B = 512 x 16B units;
    // 256 threads x 2 (rows r_lo and r_lo+64), 4 x 16B segments per row.
    const int r_lo = tid >> 2;
    const int q_lo = tid & 3;

    auto load_chunk = [&](int c, int stage) {
        const uint32_t s = sbase + (uint32_t)stage * STAGE_BYTES;
        const int kb = c * K_CHUNK;
        {
            uint32_t sa = s + (uint32_t)(r_lo * ROW_BYTES + q_lo * 16);
            CP_ASYNC16(sa, gA + (size_t)r_lo * K_DIM + kb + q_lo * 8);
            CP_ASYNC16(sa + 64 * ROW_BYTES,
                       gA + (size_t)(r_lo + 64) * K_DIM + kb + q_lo * 8);
        }
        {
            uint32_t sb = s + TILE_BYTES + (uint32_t)(r_lo * ROW_BYTES + q_lo * 16);
            CP_ASYNC16(sb, gB + (size_t)r_lo * K_DIM + kb + q_lo * 8);
            CP_ASYNC16(sb + 64 * ROW_BYTES,
                       gB + (size_t)(r_lo + 64) * K_DIM + kb + q_lo * 8);
        }
        CP_COMMIT();
    };

    float acc[2][8][4];
#pragma unroll
    for (int i = 0; i < 2; i++)
#pragma unroll
        for (int j = 0; j < 8; j++)
#pragma unroll
            for (int e = 0; e < 4; e++) acc[i][j][e] = 0.0f;

    load_chunk(0, 0);
    load_chunk(1, 1);
    load_chunk(2, 2);

    // ldmatrix lane addresses.
    // A x4: lanes 0-15 -> rows (lane&15), klo; lanes 16-31 -> same rows, khi.
    //   => mat0=(r0-7,klo) mat1=(r8-15,klo) mat2=(r0-7,khi) mat3=(r8-15,khi)
    //   == af[0..3] of the verified scalar map.
    const uint32_t a_lane = (uint32_t)((lane & 15) * ROW_BYTES + (lane >> 4) * 16);
    // B x4: lanes 0-7 n0-7 klo; 8-15 n0-7 khi; 16-23 n8-15 klo; 24-31 n8-15 khi.
    const uint32_t b_lane = (uint32_t)(((lane & 7) + ((lane >> 4) << 3)) * ROW_BYTES
                                       + (((lane >> 3) & 1) << 4));

#pragma unroll 1
    for (int c = 0; c < NUM_CHUNKS; c++) {
        CP_WAIT2();          // <=2 groups pending => group c complete
        __syncthreads();

        const uint32_t stg = sbase + (uint32_t)(c & 3) * STAGE_BYTES;
        const uint32_t As = stg + (uint32_t)(wm * 32 * ROW_BYTES) + a_lane;
        const uint32_t Bs = stg + TILE_BYTES + (uint32_t)(wn * 64 * ROW_BYTES) + b_lane;

#pragma unroll
        for (int ks = 0; ks < 2; ks++) {
            uint32_t af[2][4];
            LDMX4(af[0], As + ks * 32);
            LDMX4(af[1], As + 16 * ROW_BYTES + ks * 32);
            uint32_t bf[8][2];
#pragma unroll
            for (int jj = 0; jj < 4; jj++) {
                uint32_t t4[4];
                LDMX4(t4, Bs + jj * 16 * ROW_BYTES + ks * 32);
                bf[2 * jj][0]     = t4[0];
                bf[2 * jj][1]     = t4[1];
                bf[2 * jj + 1][0] = t4[2];
                bf[2 * jj + 1][1] = t4[3];
            }
#pragma unroll
            for (int i = 0; i < 2; i++)
#pragma unroll
                for (int j = 0; j < 8; j++)
                    MMA16816(acc[i][j], af[i], bf[j]);
        }

        // Stage (c+3)&3's previous tenant (chunk c-1) was fully read in iter
        // c-1, before this iteration's __syncthreads: safe to overwrite.
        if (c + 3 < NUM_CHUNKS) {
            load_chunk(c + 3, (c + 3) & 3);
        } else {
            CP_COMMIT();   // empty group keeps wait_group accounting correct
        }
    }

    // ---------------- Epilogue (verified R6): + pos embedding, store --------
    const int r4 = lane >> 2;
    const int qc = (lane & 3) * 2;
    const int pos_i32 = g_pos_is_i32;
    const int pad_i32 = g_pad_is_i32;
    const int* p32 = (const int*)pos_raw;
    const long long* p64 = (const long long*)pos_raw;
    const int* pd32 = (const int*)pad_raw;
    const unsigned char* pd8 = (const unsigned char*)pad_raw;

#pragma unroll
    for (int i = 0; i < 2; i++) {
#pragma unroll
        for (int rh = 0; rh < 2; rh++) {
            const int m = m_base + wm * 32 + i * 16 + rh * 8 + r4;
            int xr, yr;
            if (pos_i32) {
                xr = p32[(size_t)m * 2 + 0];
                yr = p32[(size_t)m * 2 + 1];
            } else {
                long long pxv = p64[(size_t)m * 2 + 0];
                long long pyv = p64[(size_t)m * 2 + 1];
                xr = (pxv < 0) ? 0 : (pxv > 63 ? 63 : (int)pxv);
                yr = (pyv < 0) ? 0 : (pyv > 63 ? 63 : (int)pyv);
            }
            const int xi = (xr < 0) ? 0 : (xr > 63 ? 63 : xr);
            const int yi = (yr < 0) ? 0 : (yr > 63 ? 63 : yr);
            const bool pd = pad_i32 ? (pd32[m] != 0) : (pd8[m] != 0);
            const float* t0 = table + (size_t)xi * N_DIM;
            const float* t1 = table + (size_t)(POS_SIZE + yi) * N_DIM;
            float* orow = out + (size_t)m * N_DIM;
#pragma unroll
            for (int j = 0; j < 8; j++) {
                const int n = n_base + wn * 64 + j * 8 + qc;
                float v0 = acc[i][j][rh * 2 + 0];
                float v1 = acc[i][j][rh * 2 + 1];
                if (!pd) {
                    const float2 a = *reinterpret_cast<const float2*>(t0 + n);
                    const float2 b = *reinterpret_cast<const float2*>(t1 + n);
                    v0 += a.x + b.x;
                    v1 += a.y + b.y;
                }
                float2 o; o.x = v0; o.y = v1;
                *reinterpret_cast<float2*>(orow + n) = o;
            }
        }
    }
}

// ============================================================
// Launch — inputs identified by element count (all distinct):
//   pixel_values 50331648, pos 131072, pad 65536, W 884736, table 147456
// ============================================================
extern "C" void kernel_launch(void* const* d_in, const int* in_sizes, int n_in,
                              void* d_out, int out_size) {
    const float* px = nullptr;
    const void*  pos = nullptr;
    const void*  pad = nullptr;
    const float* W = nullptr;
    const float* table = nullptr;

    for (int i = 0; i < n_in; i++) {
        switch (in_sizes[i]) {
            case 50331648: px    = (const float*)d_in[i]; break;
            case 131072:   pos   = d_in[i];               break;
            case 65536:    pad   = d_in[i];               break;
            case 884736:   W     = (const float*)d_in[i]; break;
            case 147456:   table = (const float*)d_in[i]; break;
            default: break;
        }
    }
    if (!px)    px    = (const float*)d_in[0];
    if (!pos)   pos   = d_in[1];
    if (!pad)   pad   = d_in[2];
    if (!W)     W     = (const float*)d_in[3];
    if (!table) table = (const float*)d_in[4];

    float* out = (float*)d_out;

    detect_kernel<<<2, 256>>>((const int*)pos, (const int*)pad);

    const int n4a = (M_TOTAL * K_DIM) / 4;   // 12,582,912
    const int n4b = (N_DIM * K_DIM) / 4;     // 221,184
    prep_a_kernel<<<(n4a + 255) / 256, 256>>>((const float4*)px, n4a);
    prep_b_kernel<<<(n4b + 255) / 256, 256>>>((const float4*)W, n4b);

    cudaFuncSetAttribute(gemm_kernel, cudaFuncAttributeMaxDynamicSharedMemorySize,
                         SMEM_TOTAL);
    dim3 grid(N_DIM / N_TILE, M_TOTAL / M_TILE);   // (9, 512) — N fastest: A reuse
    gemm_kernel<<<grid, 256, SMEM_TOTAL>>>(pos, pad, table, out);
}

// round 10
// speedup vs baseline: 1.5671x; 1.0771x over previous
#include <cuda_runtime.h>
#include <cuda_fp16.h>
#include <cstdint>

// ============================================================
// Problem constants
// ============================================================
#define M_TOTAL   65536          // B*NP = 16*4096
#define K_DIM     768
#define N_DIM     1152
#define POS_SIZE  64

// Tiling
#define M_TILE    128
#define N_TILE    128
#define K_CHUNK   32                       // fp16 elems per pipeline chunk
#define NUM_CHUNKS (K_DIM / K_CHUNK)       // 24
#define STAGES    4

// SMEM rows padded 64B->80B. ldmatrix row addrs r*80 mod 128 =
// {0,80,32,112,64,16,96,48} for r=0..7 -> distinct 16B banks: conflict-free.
#define ROW_BYTES   80
#define TILE_BYTES  (128 * ROW_BYTES)      // 10240
#define STAGE_BYTES (2 * TILE_BYTES)       // 20480 (A then B)
#define SMEM_TOTAL  (STAGES * STAGE_BYTES) // 81920

// ============================================================
// Scratch (device globals -- no allocation)
// ============================================================
__device__ __align__(256) __half g_A[(size_t)M_TOTAL * K_DIM];   // 96 MB
__device__ __align__(256) __half g_B[(size_t)N_DIM * K_DIM];     // 1.7 MB
__device__ int g_pos_is_i32;    // 1 if position ids are int32, 0 if int64
__device__ int g_pad_is_i32;    // 1 if padding mask is int32, 0 if 1-byte bool

// ============================================================
// Dtype detectors (verified R6/R7).
// ============================================================
__global__ void detect_kernel(const int* __restrict__ pos,
                              const int* __restrict__ padw) {
    __shared__ int sh[256];
    int acc = 0;
    if (blockIdx.x == 0) {
        for (int t = threadIdx.x; t < 2048; t += 256)
            acc |= pos[2 * t + 1];
    } else {
        for (int t = threadIdx.x; t < 16384; t += 256)
            acc |= (padw[t] & ~1);     // any bit beyond bit0 -> byte layout
    }
    sh[threadIdx.x] = acc;
    __syncthreads();
    for (int s = 128; s > 0; s >>= 1) {
        if (threadIdx.x < s) sh[threadIdx.x] |= sh[threadIdx.x + s];
        __syncthreads();
    }
    if (threadIdx.x == 0) {
        if (blockIdx.x == 0) g_pos_is_i32 = (sh[0] != 0) ? 1 : 0;
        else                 g_pad_is_i32 = (sh[0] != 0) ? 0 : 1;
    }
}

// ============================================================
// Helpers
// ============================================================
__device__ __forceinline__ uint32_t smem_u32(const void* p) {
    uint32_t a;
    asm("{ .reg .u64 t; cvta.to.shared.u64 t, %1; cvt.u32.u64 %0, t; }"
        : "=r"(a) : "l"(p));
    return a;
}

#define CP_ASYNC16(saddr, gptr) \
    asm volatile("cp.async.cg.shared.global [%0], [%1], 16;" \
                 :: "r"(saddr), "l"(gptr) : "memory")
#define CP_COMMIT() asm volatile("cp.async.commit_group;" ::: "memory")
#define CP_WAIT2()  asm volatile("cp.async.wait_group 2;" ::: "memory")

#define LDMX4(R, addr) \
    asm volatile("ldmatrix.sync.aligned.m8n8.x4.shared.b16 {%0,%1,%2,%3}, [%4];" \
        : "=r"((R)[0]), "=r"((R)[1]), "=r"((R)[2]), "=r"((R)[3]) : "r"(addr))

// mma.sync m16n8k16 row.col f32.f16.f16.f32 (verified fragment layouts)
#define MMA16816(C, A, B) \
    asm volatile("mma.sync.aligned.m16n8k16.row.col.f32.f16.f16.f32 " \
        "{%0,%1,%2,%3}, {%4,%5,%6,%7}, {%8,%9}, {%0,%1,%2,%3};" \
        : "+f"((C)[0]), "+f"((C)[1]), "+f"((C)[2]), "+f"((C)[3]) \
        : "r"((A)[0]), "r"((A)[1]), "r"((A)[2]), "r"((A)[3]), \
          "r"((B)[0]), "r"((B)[1]))

// ============================================================
// Prep kernels: fp32 -> fp16
// ============================================================
__device__ __forceinline__ uint2 cvt4(float4 v) {
    __half2 h0 = __floats2half2_rn(v.x, v.y);
    __half2 h1 = __floats2half2_rn(v.z, v.w);
    uint2 o;
    o.x = *reinterpret_cast<uint32_t*>(&h0);
    o.y = *reinterpret_cast<uint32_t*>(&h1);
    return o;
}

__global__ void prep_a_kernel(const float4* __restrict__ src, int n4) {
    int i = blockIdx.x * blockDim.x + threadIdx.x;
    if (i < n4) reinterpret_cast<uint2*>(g_A)[i] = cvt4(src[i]);
}

__global__ void prep_b_kernel(const float4* __restrict__ src, int n4) {
    int i = blockIdx.x * blockDim.x + threadIdx.x;
    if (i < n4) reinterpret_cast<uint2*>(g_B)[i] = cvt4(src[i]);
}

// ============================================================
// GEMM + positional-embedding epilogue
//   grid = (N_DIM/128, M_TOTAL/128), block = 128 (4 warps)
//   warp grid 2(m) x 2(n): warp tile 64 x 64
// ============================================================
__global__ void __launch_bounds__(128, 2) gemm_kernel(
    const void* __restrict__ pos_raw,           // [M_TOTAL, 2] i32 or i64
    const void* __restrict__ pad_raw,           // [M_TOTAL] i32 or u8
    const float* __restrict__ table,            // [2, 64, 1152] f32
    float* __restrict__ out)                    // [M_TOTAL, 1152] f32
{
    extern __shared__ char smem[];
    const uint32_t sbase = smem_u32(smem);
    const int tid  = threadIdx.x;
    const int lane = tid & 31;
    const int wid  = tid >> 5;
    const int wm   = wid & 1;          // 0..1  -> rows 64*wm
    const int wn   = wid >> 1;         // 0..1  -> cols 64*wn
    const int m_base = blockIdx.y * M_TILE;
    const int n_base = blockIdx.x * N_TILE;

    const __half* gA = g_A + (size_t)m_base * K_DIM;
    const __half* gB = g_B + (size_t)n_base * K_DIM;

    // cp.async decomposition: per tile 128 rows x 64B = 512 x 16B units;
    // 128 threads x 4 rows (r0, r0+32, r0+64, r0+96), fixed 16B segment.
    const int r0 = tid >> 2;
    const int sg = tid & 3;

    auto load_chunk = [&](int c, int stage) {
        const uint32_t s = sbase + (uint32_t)stage * STAGE_BYTES;
        const int kb = c * K_CHUNK;
#pragma unroll
        for (int k = 0; k < 4; k++) {
            const int row = r0 + 32 * k;
            uint32_t sa = s + (uint32_t)(row * ROW_BYTES + sg * 16);
            CP_ASYNC16(sa, gA + (size_t)row * K_DIM + kb + sg * 8);
            uint32_t sb = sa + TILE_BYTES;
            CP_ASYNC16(sb, gB + (size_t)row * K_DIM + kb + sg * 8);
        }
        CP_COMMIT();
    };

    float acc[4][8][4];
#pragma unroll
    for (int i = 0; i < 4; i++)
#pragma unroll
        for (int j = 0; j < 8; j++)
#pragma unroll
            for (int e = 0; e < 4; e++) acc[i][j][e] = 0.0f;

    load_chunk(0, 0);
    load_chunk(1, 1);
    load_chunk(2, 2);

    // ldmatrix lane addresses (verified R7).
    // A x4: lanes 0-15 -> rows (lane&15) klo; 16-31 -> same rows khi
    //   => af = {(r0-7,klo),(r8-15,klo),(r0-7,khi),(r8-15,khi)} = a0..a3
    const uint32_t a_lane = (uint32_t)((lane & 15) * ROW_BYTES + (lane >> 4) * 16);
    // B x4: lanes 0-7 n0-7 klo; 8-15 n0-7 khi; 16-23 n8-15 klo; 24-31 n8-15 khi
    const uint32_t b_lane = (uint32_t)(((lane & 7) + ((lane >> 4) << 3)) * ROW_BYTES
                                       + (((lane >> 3) & 1) << 4));

#pragma unroll 1
    for (int c = 0; c < NUM_CHUNKS; c++) {
        CP_WAIT2();          // <=2 groups pending => group c complete
        __syncthreads();

        const uint32_t stg = sbase + (uint32_t)(c & 3) * STAGE_BYTES;
        const uint32_t As = stg + (uint32_t)(wm * 64 * ROW_BYTES) + a_lane;
        const uint32_t Bs = stg + TILE_BYTES + (uint32_t)(wn * 64 * ROW_BYTES) + b_lane;

#pragma unroll
        for (int ks = 0; ks < 2; ks++) {
            uint32_t bf[8][2];
#pragma unroll
            for (int jj = 0; jj < 4; jj++) {
                uint32_t t4[4];
                LDMX4(t4, Bs + jj * 16 * ROW_BYTES + ks * 32);
                bf[2 * jj][0]     = t4[0];
                bf[2 * jj][1]     = t4[1];
                bf[2 * jj + 1][0] = t4[2];
                bf[2 * jj + 1][1] = t4[3];
            }
#pragma unroll
            for (int i = 0; i < 4; i++) {
                uint32_t af[4];
                LDMX4(af, As + i * 16 * ROW_BYTES + ks * 32);
#pragma unroll
                for (int j = 0; j < 8; j++)
                    MMA16816(acc[i][j], af, bf[j]);
            }
        }

        // Stage (c+3)&3's previous tenant (chunk c-1) was fully read in iter
        // c-1, before this iteration's __syncthreads: safe to overwrite.
        if (c + 3 < NUM_CHUNKS) {
            load_chunk(c + 3, (c + 3) & 3);
        } else {
            CP_COMMIT();   // empty group keeps wait_group accounting correct
        }
    }

    // ---------------- Epilogue (verified R6/R7): + pos embedding, store -----
    const int r4 = lane >> 2;
    const int qc = (lane & 3) * 2;
    const int pos_i32 = g_pos_is_i32;
    const int pad_i32 = g_pad_is_i32;
    const int* p32 = (const int*)pos_raw;
    const long long* p64 = (const long long*)pos_raw;
    const int* pd32 = (const int*)pad_raw;
    const unsigned char* pd8 = (const unsigned char*)pad_raw;

#pragma unroll
    for (int i = 0; i < 4; i++) {
#pragma unroll
        for (int rh = 0; rh < 2; rh++) {
            const int m = m_base + wm * 64 + i * 16 + rh * 8 + r4;
            int xr, yr;
            if (pos_i32) {
                xr = p32[(size_t)m * 2 + 0];
                yr = p32[(size_t)m * 2 + 1];
            } else {
                long long pxv = p64[(size_t)m * 2 + 0];
                long long pyv = p64[(size_t)m * 2 + 1];
                xr = (pxv < 0) ? 0 : (pxv > 63 ? 63 : (int)pxv);
                yr = (pyv < 0) ? 0 : (pyv > 63 ? 63 : (int)pyv);
            }
            const int xi = (xr < 0) ? 0 : (xr > 63 ? 63 : xr);
            const int yi = (yr < 0) ? 0 : (yr > 63 ? 63 : yr);
            const bool pd = pad_i32 ? (pd32[m] != 0) : (pd8[m] != 0);
            const float* t0 = table + (size_t)xi * N_DIM;
            const float* t1 = table + (size_t)(POS_SIZE + yi) * N_DIM;
            float* orow = out + (size_t)m * N_DIM;
#pragma unroll
            for (int j = 0; j < 8; j++) {
                const int n = n_base + wn * 64 + j * 8 + qc;
                float v0 = acc[i][j][rh * 2 + 0];
                float v1 = acc[i][j][rh * 2 + 1];
                if (!pd) {
                    const float2 a = *reinterpret_cast<const float2*>(t0 + n);
                    const float2 b = *reinterpret_cast<const float2*>(t1 + n);
                    v0 += a.x + b.x;
                    v1 += a.y + b.y;
                }
                float2 o; o.x = v0; o.y = v1;
                *reinterpret_cast<float2*>(orow + n) = o;
            }
        }
    }
}

// ============================================================
// Launch — inputs identified by element count (all distinct):
//   pixel_values 50331648, pos 131072, pad 65536, W 884736, table 147456
// ============================================================
extern "C" void kernel_launch(void* const* d_in, const int* in_sizes, int n_in,
                              void* d_out, int out_size) {
    const float* px = nullptr;
    const void*  pos = nullptr;
    const void*  pad = nullptr;
    const float* W = nullptr;
    const float* table = nullptr;

    for (int i = 0; i < n_in; i++) {
        switch (in_sizes[i]) {
            case 50331648: px    = (const float*)d_in[i]; break;
            case 131072:   pos   = d_in[i];               break;
            case 65536:    pad   = d_in[i];               break;
            case 884736:   W     = (const float*)d_in[i]; break;
            case 147456:   table = (const float*)d_in[i]; break;
            default: break;
        }
    }
    if (!px)    px    = (const float*)d_in[0];
    if (!pos)   pos   = d_in[1];
    if (!pad)   pad   = d_in[2];
    if (!W)     W     = (const float*)d_in[3];
    if (!table) table = (const float*)d_in[4];

    float* out = (float*)d_out;

    detect_kernel<<<2, 256>>>((const int*)pos, (const int*)pad);

    const int n4a = (M_TOTAL * K_DIM) / 4;   // 12,582,912
    const int n4b = (N_DIM * K_DIM) / 4;     // 221,184
    prep_a_kernel<<<(n4a + 255) / 256, 256>>>((const float4*)px, n4a);
    prep_b_kernel<<<(n4b + 255) / 256, 256>>>((const float4*)W, n4b);

    cudaFuncSetAttribute(gemm_kernel, cudaFuncAttributeMaxDynamicSharedMemorySize,
                         SMEM_TOTAL);
    dim3 grid(N_DIM / N_TILE, M_TOTAL / M_TILE);   // (9, 512) — N fastest: A reuse
    gemm_kernel<<<grid, 128, SMEM_TOTAL>>>(pos, pad, table, out);
}

// round 11
// speedup vs baseline: 1.6370x; 1.0446x over previous
#include <cuda_runtime.h>
#include <cuda_fp16.h>
#include <cstdint>

// ============================================================
// Problem constants
// ============================================================
#define M_TOTAL   65536          // B*NP = 16*4096
#define K_DIM     768
#define N_DIM     1152
#define POS_SIZE  64

// Tiling
#define M_TILE    128
#define N_TILE    128
#define K_CHUNK   64                       // fp16 elems per pipeline chunk
#define NUM_CHUNKS (K_DIM / K_CHUNK)       // 12
#define STAGES    3

// SMEM rows: 128B data + 16B pad = 144B. ldmatrix row addrs r*144 mod 128 =
// 16r mod 128 -> distinct for r=0..7 (and +8 rows add 1152 ≡ 0): conflict-free.
#define ROW_BYTES   144
#define TILE_BYTES  (128 * ROW_BYTES)      // 18432
#define STAGE_BYTES (2 * TILE_BYTES)       // 36864 (A then B)
#define SMEM_TOTAL  (STAGES * STAGE_BYTES) // 110592  (2 CTAs = 216 KB <= 228 KB)

// ============================================================
// Scratch (device globals -- no allocation)
// ============================================================
__device__ __align__(256) __half g_A[(size_t)M_TOTAL * K_DIM];   // 96 MB
__device__ __align__(256) __half g_B[(size_t)N_DIM * K_DIM];     // 1.7 MB
__device__ int g_pos_is_i32;    // 1 if position ids are int32, 0 if int64
__device__ int g_pad_is_i32;    // 1 if padding mask is int32, 0 if 1-byte bool

// ============================================================
// Dtype detectors (verified R6-R8).
// ============================================================
__global__ void detect_kernel(const int* __restrict__ pos,
                              const int* __restrict__ padw) {
    __shared__ int sh[256];
    int acc = 0;
    if (blockIdx.x == 0) {
        for (int t = threadIdx.x; t < 2048; t += 256)
            acc |= pos[2 * t + 1];
    } else {
        for (int t = threadIdx.x; t < 16384; t += 256)
            acc |= (padw[t] & ~1);     // any bit beyond bit0 -> byte layout
    }
    sh[threadIdx.x] = acc;
    __syncthreads();
    for (int s = 128; s > 0; s >>= 1) {
        if (threadIdx.x < s) sh[threadIdx.x] |= sh[threadIdx.x + s];
        __syncthreads();
    }
    if (threadIdx.x == 0) {
        if (blockIdx.x == 0) g_pos_is_i32 = (sh[0] != 0) ? 1 : 0;
        else                 g_pad_is_i32 = (sh[0] != 0) ? 0 : 1;
    }
}

// ============================================================
// Helpers
// ============================================================
__device__ __forceinline__ uint32_t smem_u32(const void* p) {
    uint32_t a;
    asm("{ .reg .u64 t; cvta.to.shared.u64 t, %1; cvt.u32.u64 %0, t; }"
        : "=r"(a) : "l"(p));
    return a;
}

#define CP_ASYNC16(saddr, gptr) \
    asm volatile("cp.async.cg.shared.global [%0], [%1], 16;" \
                 :: "r"(saddr), "l"(gptr) : "memory")
#define CP_COMMIT() asm volatile("cp.async.commit_group;" ::: "memory")
#define CP_WAIT1()  asm volatile("cp.async.wait_group 1;" ::: "memory")

#define LDMX4(R, addr) \
    asm volatile("ldmatrix.sync.aligned.m8n8.x4.shared.b16 {%0,%1,%2,%3}, [%4];" \
        : "=r"((R)[0]), "=r"((R)[1]), "=r"((R)[2]), "=r"((R)[3]) : "r"(addr))

// mma.sync m16n8k16 row.col f32.f16.f16.f32 (verified fragment layouts)
#define MMA16816(C, A, B) \
    asm volatile("mma.sync.aligned.m16n8k16.row.col.f32.f16.f16.f32 " \
        "{%0,%1,%2,%3}, {%4,%5,%6,%7}, {%8,%9}, {%0,%1,%2,%3};" \
        : "+f"((C)[0]), "+f"((C)[1]), "+f"((C)[2]), "+f"((C)[3]) \
        : "r"((A)[0]), "r"((A)[1]), "r"((A)[2]), "r"((A)[3]), \
          "r"((B)[0]), "r"((B)[1]))

// ============================================================
// Prep kernels: fp32 -> fp16
// ============================================================
__device__ __forceinline__ uint2 cvt4(float4 v) {
    __half2 h0 = __floats2half2_rn(v.x, v.y);
    __half2 h1 = __floats2half2_rn(v.z, v.w);
    uint2 o;
    o.x = *reinterpret_cast<uint32_t*>(&h0);
    o.y = *reinterpret_cast<uint32_t*>(&h1);
    return o;
}

__global__ void prep_a_kernel(const float4* __restrict__ src, int n4) {
    int i = blockIdx.x * blockDim.x + threadIdx.x;
    if (i < n4) reinterpret_cast<uint2*>(g_A)[i] = cvt4(src[i]);
}

__global__ void prep_b_kernel(const float4* __restrict__ src, int n4) {
    int i = blockIdx.x * blockDim.x + threadIdx.x;
    if (i < n4) reinterpret_cast<uint2*>(g_B)[i] = cvt4(src[i]);
}

// ============================================================
// GEMM + positional-embedding epilogue
//   grid = (N_DIM/128, M_TOTAL/128), block = 128 (4 warps)
//   warp grid 2(m) x 2(n): warp tile 64 x 64
// ============================================================
__global__ void __launch_bounds__(128, 2) gemm_kernel(
    const void* __restrict__ pos_raw,           // [M_TOTAL, 2] i32 or i64
    const void* __restrict__ pad_raw,           // [M_TOTAL] i32 or u8
    const float* __restrict__ table,            // [2, 64, 1152] f32
    float* __restrict__ out)                    // [M_TOTAL, 1152] f32
{
    extern __shared__ char smem[];
    const uint32_t sbase = smem_u32(smem);
    const int tid  = threadIdx.x;
    const int lane = tid & 31;
    const int wid  = tid >> 5;
    const int wm   = wid & 1;          // 0..1  -> rows 64*wm
    const int wn   = wid >> 1;         // 0..1  -> cols 64*wn
    const int m_base = blockIdx.y * M_TILE;
    const int n_base = blockIdx.x * N_TILE;

    const __half* gA = g_A + (size_t)m_base * K_DIM;
    const __half* gB = g_B + (size_t)n_base * K_DIM;

    // cp.async decomposition: per tile 128 rows x 128B = 1024 x 16B units;
    // 128 threads x 8 units (unit u = tid + 128*t: row = u>>3, seg = u&7).
    auto load_chunk = [&](int c, int stage) {
        const uint32_t s = sbase + (uint32_t)stage * STAGE_BYTES;
        const int kb = c * K_CHUNK;
#pragma unroll
        for (int t = 0; t < 8; t++) {
            const int u = tid + 128 * t;
            const int row = u >> 3, sg = u & 7;
            uint32_t sa = s + (uint32_t)(row * ROW_BYTES + sg * 16);
            CP_ASYNC16(sa, gA + (size_t)row * K_DIM + kb + sg * 8);
            CP_ASYNC16(sa + TILE_BYTES, gB + (size_t)row * K_DIM + kb + sg * 8);
        }
        CP_COMMIT();
    };

    float acc[4][8][4];
#pragma unroll
    for (int i = 0; i < 4; i++)
#pragma unroll
        for (int j = 0; j < 8; j++)
#pragma unroll
            for (int e = 0; e < 4; e++) acc[i][j][e] = 0.0f;

    load_chunk(0, 0);
    load_chunk(1, 1);

    // ldmatrix lane addresses (verified R7/R8), ROW_BYTES=144.
    const uint32_t a_lane = (uint32_t)((lane & 15) * ROW_BYTES + (lane >> 4) * 16);
    const uint32_t b_lane = (uint32_t)(((lane & 7) + ((lane >> 4) << 3)) * ROW_BYTES
                                       + (((lane >> 3) & 1) << 4));

#pragma unroll 1
    for (int c = 0; c < NUM_CHUNKS; c++) {
        CP_WAIT1();          // <=1 group pending => group c complete
        __syncthreads();

        const uint32_t stg = sbase + (uint32_t)(c % 3) * STAGE_BYTES;
        const uint32_t As = stg + (uint32_t)(wm * 64 * ROW_BYTES) + a_lane;
        const uint32_t Bs = stg + TILE_BYTES + (uint32_t)(wn * 64 * ROW_BYTES) + b_lane;

        // B-fragment double buffer across the 4 ks-steps.
        uint32_t bf[2][8][2];
        {
#pragma unroll
            for (int jj = 0; jj < 4; jj++) {
                uint32_t t4[4];
                LDMX4(t4, Bs + jj * 16 * ROW_BYTES);
                bf[0][2 * jj][0]     = t4[0];
                bf[0][2 * jj][1]     = t4[1];
                bf[0][2 * jj + 1][0] = t4[2];
                bf[0][2 * jj + 1][1] = t4[3];
            }
        }
#pragma unroll
        for (int ks = 0; ks < 4; ks++) {
            const int cur = ks & 1;
            if (ks < 3) {
                const int nxt = cur ^ 1;
#pragma unroll
                for (int jj = 0; jj < 4; jj++) {
                    uint32_t t4[4];
                    LDMX4(t4, Bs + jj * 16 * ROW_BYTES + (ks + 1) * 32);
                    bf[nxt][2 * jj][0]     = t4[0];
                    bf[nxt][2 * jj][1]     = t4[1];
                    bf[nxt][2 * jj + 1][0] = t4[2];
                    bf[nxt][2 * jj + 1][1] = t4[3];
                }
            }
#pragma unroll
            for (int i = 0; i < 4; i++) {
                uint32_t af[4];
                LDMX4(af, As + i * 16 * ROW_BYTES + ks * 32);
#pragma unroll
                for (int j = 0; j < 8; j++)
                    MMA16816(acc[i][j], af, bf[cur][j]);
            }
        }

        // Stage (c+2)%3's previous tenant (chunk c-1) was fully read in iter
        // c-1, before this iteration's __syncthreads: safe to overwrite.
        if (c + 2 < NUM_CHUNKS) {
            load_chunk(c + 2, (c + 2) % 3);
        } else {
            CP_COMMIT();   // empty group keeps wait_group accounting correct
        }
    }

    // ---------------- Epilogue (verified R6-R8): + pos embedding, store -----
    const int r4 = lane >> 2;
    const int qc = (lane & 3) * 2;
    const int pos_i32 = g_pos_is_i32;
    const int pad_i32 = g_pad_is_i32;
    const int* p32 = (const int*)pos_raw;
    const long long* p64 = (const long long*)pos_raw;
    const int* pd32 = (const int*)pad_raw;
    const unsigned char* pd8 = (const unsigned char*)pad_raw;

#pragma unroll
    for (int i = 0; i < 4; i++) {
#pragma unroll
        for (int rh = 0; rh < 2; rh++) {
            const int m = m_base + wm * 64 + i * 16 + rh * 8 + r4;
            int xr, yr;
            if (pos_i32) {
                xr = p32[(size_t)m * 2 + 0];
                yr = p32[(size_t)m * 2 + 1];
            } else {
                long long pxv = p64[(size_t)m * 2 + 0];
                long long pyv = p64[(size_t)m * 2 + 1];
                xr = (pxv < 0) ? 0 : (pxv > 63 ? 63 : (int)pxv);
                yr = (pyv < 0) ? 0 : (pyv > 63 ? 63 : (int)pyv);
            }
            const int xi = (xr < 0) ? 0 : (xr > 63 ? 63 : xr);
            const int yi = (yr < 0) ? 0 : (yr > 63 ? 63 : yr);
            const bool pd = pad_i32 ? (pd32[m] != 0) : (pd8[m] != 0);
            const float* t0 = table + (size_t)xi * N_DIM;
            const float* t1 = table + (size_t)(POS_SIZE + yi) * N_DIM;
            float* orow = out + (size_t)m * N_DIM;
#pragma unroll
            for (int j = 0; j < 8; j++) {
                const int n = n_base + wn * 64 + j * 8 + qc;
                float v0 = acc[i][j][rh * 2 + 0];
                float v1 = acc[i][j][rh * 2 + 1];
                if (!pd) {
                    const float2 a = *reinterpret_cast<const float2*>(t0 + n);
                    const float2 b = *reinterpret_cast<const float2*>(t1 + n);
                    v0 += a.x + b.x;
                    v1 += a.y + b.y;
                }
                float2 o; o.x = v0; o.y = v1;
                *reinterpret_cast<float2*>(orow + n) = o;
            }
        }
    }
}

// ============================================================
// Launch — inputs identified by element count (all distinct):
//   pixel_values 50331648, pos 131072, pad 65536, W 884736, table 147456
// ============================================================
extern "C" void kernel_launch(void* const* d_in, const int* in_sizes, int n_in,
                              void* d_out, int out_size) {
    const float* px = nullptr;
    const void*  pos = nullptr;
    const void*  pad = nullptr;
    const float* W = nullptr;
    const float* table = nullptr;

    for (int i = 0; i < n_in; i++) {
        switch (in_sizes[i]) {
            case 50331648: px    = (const float*)d_in[i]; break;
            case 131072:   pos   = d_in[i];               break;
            case 65536:    pad   = d_in[i];               break;
            case 884736:   W     = (const float*)d_in[i]; break;
            case 147456:   table = (const float*)d_in[i]; break;
            default: break;
        }
    }
    if (!px)    px    = (const float*)d_in[0];
    if (!pos)   pos   = d_in[1];
    if (!pad)   pad   = d_in[2];
    if (!W)     W     = (const float*)d_in[3];
    if (!table) table = (const float*)d_in[4];

    float* out = (float*)d_out;

    detect_kernel<<<2, 256>>>((const int*)pos, (const int*)pad);

    const int n4a = (M_TOTAL * K_DIM) / 4;   // 12,582,912
    const int n4b = (N_DIM * K_DIM) / 4;     // 221,184
    prep_a_kernel<<<(n4a + 255) / 256, 256>>>((const float4*)px, n4a);
    prep_b_kernel<<<(n4b + 255) / 256, 256>>>((const float4*)W, n4b);

    cudaFuncSetAttribute(gemm_kernel, cudaFuncAttributeMaxDynamicSharedMemorySize,
                         SMEM_TOTAL);
    dim3 grid(N_DIM / N_TILE, M_TOTAL / M_TILE);   // (9, 512) — N fastest: A reuse
    gemm_kernel<<<grid, 128, SMEM_TOTAL>>>(pos, pad, table, out);
}